// round 2
// baseline (speedup 1.0000x reference)
#include <cuda_runtime.h>
#include <float.h>

#define NQ    16384
#define HID   128
#define PROP  64
#define SPACE 4
#define KNN   40
#define NPART 8
#define CPART (NQ / NPART)   // 2048 candidates per partition
#define QB    128            // queries per knn block
#define TJ    128            // candidate tile in smem

// ---------------- scratch (device globals; no allocation allowed) ----------------
__device__ float g_t1[NQ * HID];
__device__ float g_t2[NQ * HID];
__device__ float g_xcat[NQ * 256];     // [x (128) | agg_mean (64) | agg_max (64)]
__device__ float g_xg[NQ * HID];
__device__ float g_s[NQ * SPACE];
__device__ float g_s2[NQ];
__device__ float g_h[NQ * PROP];
__device__ float g_pd[NPART * KNN * NQ];  // partial top-k dists, layout [t][q]
__device__ int   g_pj[NPART * KNN * NQ];  // partial top-k indices, layout [t][q]
__device__ float g_kd[NQ * KNN];
__device__ int   g_kj[NQ * KNN];

// ---------------- generic fp32 GEMM: C = act(A[M,Kd] @ W[Kd,Nd] + b) --------------
// BM=64, BN=128, BK=16, 256 threads, thread tile 8x4.
__global__ __launch_bounds__(256) void gemm_kernel(
    const float* __restrict__ A, int lda,
    const float* __restrict__ W,          // row-major [Kd, Nd]
    const float* __restrict__ bias,
    float* __restrict__ C, int ldc,
    int Kd, int Nd, int relu)
{
    __shared__ float As[64][16];     // [m][k]  (64B rows: STS.128 conflict-free)
    __shared__ float Bs[16][128];    // [k][n]

    const int tid = threadIdx.x;
    const int m0  = blockIdx.x * 64;
    const int tn  = tid & 31;       // 32 thread-cols * 4 = 128
    const int tm  = tid >> 5;       // 8 thread-rows * 8 = 64

    float acc[8][4];
#pragma unroll
    for (int i = 0; i < 8; i++)
#pragma unroll
        for (int j = 0; j < 4; j++) acc[i][j] = 0.f;

    const int arow = tid >> 2;          // 0..63
    const int ak   = (tid & 3) * 4;     // 0,4,8,12
    const int bn   = (tid & 31) * 4;    // 0..124
    const int bk   = tid >> 5;          // 0..7

    for (int k0 = 0; k0 < Kd; k0 += 16) {
        // A tile 64x16: one float4 per thread (scalar-guarded for Kd=9 / lda=9)
        {
            const float* ap = A + (long)(m0 + arow) * lda + k0 + ak;
            float4 v;
            v.x = (k0 + ak + 0 < Kd) ? ap[0] : 0.f;
            v.y = (k0 + ak + 1 < Kd) ? ap[1] : 0.f;
            v.z = (k0 + ak + 2 < Kd) ? ap[2] : 0.f;
            v.w = (k0 + ak + 3 < Kd) ? ap[3] : 0.f;
            *(float4*)&As[arow][ak] = v;
        }
        // B tile 16x128: two float4 per thread
#pragma unroll
        for (int r = 0; r < 2; r++) {
            int kk = bk + r * 8;
            float4 v = make_float4(0.f, 0.f, 0.f, 0.f);
            if (k0 + kk < Kd) {
                const float* wp = W + (long)(k0 + kk) * Nd + bn;
                if (bn + 0 < Nd) v.x = wp[0];
                if (bn + 1 < Nd) v.y = wp[1];
                if (bn + 2 < Nd) v.z = wp[2];
                if (bn + 3 < Nd) v.w = wp[3];
            }
            *(float4*)&Bs[kk][bn] = v;
        }
        __syncthreads();

#pragma unroll
        for (int kk4 = 0; kk4 < 16; kk4 += 4) {
            float4 b0 = *(const float4*)&Bs[kk4 + 0][tn * 4];
            float4 b1 = *(const float4*)&Bs[kk4 + 1][tn * 4];
            float4 b2 = *(const float4*)&Bs[kk4 + 2][tn * 4];
            float4 b3 = *(const float4*)&Bs[kk4 + 3][tn * 4];
#pragma unroll
            for (int i = 0; i < 8; i++) {
                float4 a = *(const float4*)&As[tm * 8 + i][kk4];  // broadcast
                acc[i][0] = fmaf(a.x, b0.x, acc[i][0]);
                acc[i][1] = fmaf(a.x, b0.y, acc[i][1]);
                acc[i][2] = fmaf(a.x, b0.z, acc[i][2]);
                acc[i][3] = fmaf(a.x, b0.w, acc[i][3]);
                acc[i][0] = fmaf(a.y, b1.x, acc[i][0]);
                acc[i][1] = fmaf(a.y, b1.y, acc[i][1]);
                acc[i][2] = fmaf(a.y, b1.z, acc[i][2]);
                acc[i][3] = fmaf(a.y, b1.w, acc[i][3]);
                acc[i][0] = fmaf(a.z, b2.x, acc[i][0]);
                acc[i][1] = fmaf(a.z, b2.y, acc[i][1]);
                acc[i][2] = fmaf(a.z, b2.z, acc[i][2]);
                acc[i][3] = fmaf(a.z, b2.w, acc[i][3]);
                acc[i][0] = fmaf(a.w, b3.x, acc[i][0]);
                acc[i][1] = fmaf(a.w, b3.y, acc[i][1]);
                acc[i][2] = fmaf(a.w, b3.z, acc[i][2]);
                acc[i][3] = fmaf(a.w, b3.w, acc[i][3]);
            }
        }
        __syncthreads();
    }

#pragma unroll
    for (int i = 0; i < 8; i++) {
        int row = m0 + tm * 8 + i;
#pragma unroll
        for (int j = 0; j < 4; j++) {
            int col = tn * 4 + j;
            if (col < Nd) {
                float v = acc[i][j] + bias[col];
                if (relu) v = fmaxf(v, 0.f);
                C[(long)row * ldc + col] = v;
            }
        }
    }
}

// ---------------- s2 norms ----------------
__global__ void s2_kernel(const float4* __restrict__ s, float* __restrict__ s2)
{
    int i = blockIdx.x * blockDim.x + threadIdx.x;
    float4 v = s[i];
    s2[i] = v.x * v.x + v.y * v.y + v.z * v.z + v.w * v.w;
}

// ---------------- kNN: per-partition top-40 (1 thread = 1 query) ----------------
__global__ __launch_bounds__(QB) void knn_part_kernel(
    const float4* __restrict__ s, const float* __restrict__ s2,
    float* __restrict__ pd, int* __restrict__ pj)
{
    __shared__ float4 sj[TJ];
    __shared__ float  s2j[TJ];

    const int tid  = threadIdx.x;
    const int q    = blockIdx.x * QB + tid;
    const int part = blockIdx.y;

    const float4 si = s[q];
    const float m2x = -2.f * si.x, m2y = -2.f * si.y;
    const float m2z = -2.f * si.z, m2w = -2.f * si.w;
    const float s2i = s2[q];

    float hd[KNN]; int hj[KNN];
#pragma unroll
    for (int k = 0; k < KNN; k++) { hd[k] = FLT_MAX; hj[k] = 0x7FFFFFFF; }
    float thr = FLT_MAX;  // hd[0] - s2i (FLT_MAX - finite rounds to FLT_MAX)

    const int base = part * CPART;
    for (int t0 = 0; t0 < CPART; t0 += TJ) {
        sj[tid]  = s[base + t0 + tid];
        s2j[tid] = s2[base + t0 + tid];
        __syncthreads();
#pragma unroll 4
        for (int jj = 0; jj < TJ; jj++) {
            float4 c = sj[jj];
            float v = fmaf(m2x, c.x, s2j[jj]);
            v = fmaf(m2y, c.y, v);
            v = fmaf(m2z, c.z, v);
            v = fmaf(m2w, c.w, v);
            if (v < thr) {                 // d2 < current worst-of-40
                float d2 = v + s2i;
                int   jg = base + t0 + jj;
                int k = 0;                 // replace root of max-heap, sift down
                for (;;) {
                    int c1 = 2 * k + 1;
                    if (c1 >= KNN) break;
                    int c2 = c1 + 1;
                    if (c2 < KNN && hd[c2] > hd[c1]) c1 = c2;
                    if (hd[c1] <= d2) break;
                    hd[k] = hd[c1]; hj[k] = hj[c1]; k = c1;
                }
                hd[k] = d2; hj[k] = jg;
                thr = hd[0] - s2i;
            }
        }
        __syncthreads();
    }

    const int tb = part * KNN;
#pragma unroll
    for (int k = 0; k < KNN; k++) {        // [t][q] layout -> coalesced
        pd[(tb + k) * NQ + q] = hd[k];
        pj[(tb + k) * NQ + q] = hj[k];
    }
}

// ---------------- merge 8 partial lists -> global top-40 (lexicographic) ---------
__global__ void knn_merge_kernel(
    const float* __restrict__ pd, const int* __restrict__ pj,
    float* __restrict__ kd, int* __restrict__ kj)
{
    int q = blockIdx.x * blockDim.x + threadIdx.x;
    float hd[KNN]; int hj[KNN];
#pragma unroll
    for (int k = 0; k < KNN; k++) { hd[k] = FLT_MAX; hj[k] = 0x7FFFFFFF; }

    for (int t = 0; t < NPART * KNN; t++) {
        float v = pd[t * NQ + q];          // coalesced across q
        int   j = pj[t * NQ + q];
        if (v < hd[0] || (v == hd[0] && j < hj[0])) {
            int k = 0;
            for (;;) {
                int c1 = 2 * k + 1;
                if (c1 >= KNN) break;
                int c2 = c1 + 1;
                if (c2 < KNN && (hd[c2] > hd[c1] ||
                                 (hd[c2] == hd[c1] && hj[c2] > hj[c1]))) c1 = c2;
                if (hd[c1] < v || (hd[c1] == v && hj[c1] < j)) break;
                hd[k] = hd[c1]; hj[k] = hj[c1]; k = c1;
            }
            hd[k] = v; hj[k] = j;
        }
    }
#pragma unroll
    for (int k = 0; k < KNN; k++) {
        kd[q * KNN + k] = hd[k];
        kj[q * KNN + k] = hj[k];
    }
}

// ---------------- aggregate: warp per query, mean||max of h[idx]*w ---------------
__global__ void aggregate_kernel(
    const float* __restrict__ h, const float* __restrict__ kd,
    const int* __restrict__ kj, float* __restrict__ xcat)
{
    int gw   = (blockIdx.x * blockDim.x + threadIdx.x) >> 5;  // query
    int lane = threadIdx.x & 31;

    const float* dd = kd + gw * KNN;
    const int*   jj = kj + gw * KNN;

    float m0 = 0.f, m1 = 0.f;
    float x0 = -FLT_MAX, x1 = -FLT_MAX;
#pragma unroll
    for (int k = 0; k < KNN; k++) {
        int   j = jj[k];                                  // broadcast load
        float w = expf(-10.f * fmaxf(dd[k], 0.f));
        float v0 = h[j * PROP + lane] * w;                // coalesced 128B
        float v1 = h[j * PROP + 32 + lane] * w;
        m0 += v0; m1 += v1;
        x0 = fmaxf(x0, v0); x1 = fmaxf(x1, v1);
    }
    float* out = xcat + (long)gw * 256 + 128;
    const float inv = 1.f / (float)KNN;
    out[lane]      = m0 * inv;
    out[32 + lane] = m1 * inv;
    out[64 + lane] = x0;
    out[96 + lane] = x1;
}

// =================================================================================
extern "C" void kernel_launch(void* const* d_in, const int* in_sizes, int n_in,
                              void* d_out, int out_size)
{
    const float* x    = (const float*)d_in[0];
    const float* fc1W = (const float*)d_in[1];
    const float* fc1b = (const float*)d_in[2];
    const float* fc2W = (const float*)d_in[3];
    const float* fc2b = (const float*)d_in[4];
    const float* gsW  = (const float*)d_in[5];
    const float* gsb  = (const float*)d_in[6];
    const float* ghW  = (const float*)d_in[7];
    const float* ghb  = (const float*)d_in[8];
    const float* goW  = (const float*)d_in[9];
    const float* gob  = (const float*)d_in[10];
    const float* d1W  = (const float*)d_in[11];
    const float* d1b  = (const float*)d_in[12];
    const float* d2W  = (const float*)d_in[13];
    const float* d2b  = (const float*)d_in[14];
    const float* d3W  = (const float*)d_in[15];
    const float* d3b  = (const float*)d_in[16];
    const float* fc3W = (const float*)d_in[17];
    const float* fc3b = (const float*)d_in[18];
    const float* fc4W = (const float*)d_in[19];
    const float* fc4b = (const float*)d_in[20];
    float* out = (float*)d_out;

    float *t1, *t2, *xcat, *xg, *s, *s2n, *h, *pd, *kd;
    int *pj, *kj;
    cudaGetSymbolAddress((void**)&t1,   g_t1);
    cudaGetSymbolAddress((void**)&t2,   g_t2);
    cudaGetSymbolAddress((void**)&xcat, g_xcat);
    cudaGetSymbolAddress((void**)&xg,   g_xg);
    cudaGetSymbolAddress((void**)&s,    g_s);
    cudaGetSymbolAddress((void**)&s2n,  g_s2);
    cudaGetSymbolAddress((void**)&h,    g_h);
    cudaGetSymbolAddress((void**)&pd,   g_pd);
    cudaGetSymbolAddress((void**)&pj,   g_pj);
    cudaGetSymbolAddress((void**)&kd,   g_kd);
    cudaGetSymbolAddress((void**)&kj,   g_kj);

    const int GB = NQ / 64;  // gemm grid

    // fc1, fc2 (x lives in xcat[:, :128] with row stride 256 from here on)
    gemm_kernel<<<GB, 256>>>(x, 9, fc1W, fc1b, t1, HID, 9, HID, 1);
    gemm_kernel<<<GB, 256>>>(t1, HID, fc2W, fc2b, xcat, 256, HID, HID, 1);

    for (int l = 0; l < 4; l++) {
        gemm_kernel<<<GB, 256>>>(xcat, 256, gsW + l * HID * SPACE, gsb + l * SPACE,
                                 s, SPACE, HID, SPACE, 0);
        gemm_kernel<<<GB, 256>>>(xcat, 256, ghW + l * HID * PROP, ghb + l * PROP,
                                 h, PROP, HID, PROP, 0);
        s2_kernel<<<NQ / 256, 256>>>((const float4*)s, s2n);
        knn_part_kernel<<<dim3(NQ / QB, NPART), QB>>>((const float4*)s, s2n, pd, pj);
        knn_merge_kernel<<<NQ / 128, 128>>>(pd, pj, kd, kj);
        aggregate_kernel<<<NQ / 8, 256>>>(h, kd, kj, xcat);
        // lin_out: [x | mean | max] (Kd=256) -> xg
        gemm_kernel<<<GB, 256>>>(xcat, 256, goW + l * 256 * HID, gob + l * HID,
                                 xg, HID, 256, HID, 0);
        gemm_kernel<<<GB, 256>>>(xg, HID, d1W + l * HID * HID, d1b + l * HID,
                                 t1, HID, HID, HID, 1);
        gemm_kernel<<<GB, 256>>>(t1, HID, d2W + l * HID * HID, d2b + l * HID,
                                 t2, HID, HID, HID, 1);
        gemm_kernel<<<GB, 256>>>(t2, HID, d3W + l * HID * HID, d3b + l * HID,
                                 xcat, 256, HID, HID, 1);
    }

    gemm_kernel<<<GB, 256>>>(xcat, 256, fc3W, fc3b, t1, HID, HID, HID, 1);
    gemm_kernel<<<GB, 256>>>(t1, HID, fc4W, fc4b, out, 4, HID, 4, 0);
}

// round 3
// speedup vs baseline: 6.6442x; 6.6442x over previous
#include <cuda_runtime.h>
#include <float.h>

#define NQ    16384
#define HID   128
#define PROP  64
#define SPACE 4
#define KNN   40
#define TJ    512            // candidate tile in smem (knn)
#define WPB   16             // warps (=queries) per knn block

// ---------------- scratch (device globals; no allocation allowed) ----------------
__device__ float g_t1[NQ * HID];
__device__ float g_t2[NQ * HID];
__device__ float g_xcat[NQ * 256];     // [x (128) | agg_mean (64) | agg_max (64)]
__device__ float g_xg[NQ * HID];
__device__ float g_s[NQ * SPACE];
__device__ float g_s2[NQ];
__device__ float g_h[NQ * PROP];
__device__ float g_kd[NQ * KNN];
__device__ int   g_kj[NQ * KNN];

// ---------------- generic fp32 GEMM: C = act(A[M,Kd] @ W[Kd,Nd] + b) --------------
// BM=64, BN=128, BK=16, 256 threads, thread tile 8x4.
__global__ __launch_bounds__(256) void gemm_kernel(
    const float* __restrict__ A, int lda,
    const float* __restrict__ W,          // row-major [Kd, Nd]
    const float* __restrict__ bias,
    float* __restrict__ C, int ldc,
    int Kd, int Nd, int relu)
{
    __shared__ float As[64][16];     // [m][k]
    __shared__ float Bs[16][128];    // [k][n]

    const int tid = threadIdx.x;
    const int m0  = blockIdx.x * 64;
    const int tn  = tid & 31;       // 32 thread-cols * 4 = 128
    const int tm  = tid >> 5;       // 8 thread-rows * 8 = 64

    float acc[8][4];
#pragma unroll
    for (int i = 0; i < 8; i++)
#pragma unroll
        for (int j = 0; j < 4; j++) acc[i][j] = 0.f;

    const int arow = tid >> 2;          // 0..63
    const int ak   = (tid & 3) * 4;     // 0,4,8,12
    const int bn   = (tid & 31) * 4;    // 0..124
    const int bk   = tid >> 5;          // 0..7

    for (int k0 = 0; k0 < Kd; k0 += 16) {
        {
            const float* ap = A + (long)(m0 + arow) * lda + k0 + ak;
            float4 v;
            v.x = (k0 + ak + 0 < Kd) ? ap[0] : 0.f;
            v.y = (k0 + ak + 1 < Kd) ? ap[1] : 0.f;
            v.z = (k0 + ak + 2 < Kd) ? ap[2] : 0.f;
            v.w = (k0 + ak + 3 < Kd) ? ap[3] : 0.f;
            *(float4*)&As[arow][ak] = v;
        }
#pragma unroll
        for (int r = 0; r < 2; r++) {
            int kk = bk + r * 8;
            float4 v = make_float4(0.f, 0.f, 0.f, 0.f);
            if (k0 + kk < Kd) {
                const float* wp = W + (long)(k0 + kk) * Nd + bn;
                if (bn + 0 < Nd) v.x = wp[0];
                if (bn + 1 < Nd) v.y = wp[1];
                if (bn + 2 < Nd) v.z = wp[2];
                if (bn + 3 < Nd) v.w = wp[3];
            }
            *(float4*)&Bs[kk][bn] = v;
        }
        __syncthreads();

#pragma unroll
        for (int kk4 = 0; kk4 < 16; kk4 += 4) {
            float4 b0 = *(const float4*)&Bs[kk4 + 0][tn * 4];
            float4 b1 = *(const float4*)&Bs[kk4 + 1][tn * 4];
            float4 b2 = *(const float4*)&Bs[kk4 + 2][tn * 4];
            float4 b3 = *(const float4*)&Bs[kk4 + 3][tn * 4];
#pragma unroll
            for (int i = 0; i < 8; i++) {
                float4 a = *(const float4*)&As[tm * 8 + i][kk4];
                acc[i][0] = fmaf(a.x, b0.x, acc[i][0]);
                acc[i][1] = fmaf(a.x, b0.y, acc[i][1]);
                acc[i][2] = fmaf(a.x, b0.z, acc[i][2]);
                acc[i][3] = fmaf(a.x, b0.w, acc[i][3]);
                acc[i][0] = fmaf(a.y, b1.x, acc[i][0]);
                acc[i][1] = fmaf(a.y, b1.y, acc[i][1]);
                acc[i][2] = fmaf(a.y, b1.z, acc[i][2]);
                acc[i][3] = fmaf(a.y, b1.w, acc[i][3]);
                acc[i][0] = fmaf(a.z, b2.x, acc[i][0]);
                acc[i][1] = fmaf(a.z, b2.y, acc[i][1]);
                acc[i][2] = fmaf(a.z, b2.z, acc[i][2]);
                acc[i][3] = fmaf(a.z, b2.w, acc[i][3]);
                acc[i][0] = fmaf(a.w, b3.x, acc[i][0]);
                acc[i][1] = fmaf(a.w, b3.y, acc[i][1]);
                acc[i][2] = fmaf(a.w, b3.z, acc[i][2]);
                acc[i][3] = fmaf(a.w, b3.w, acc[i][3]);
            }
        }
        __syncthreads();
    }

#pragma unroll
    for (int i = 0; i < 8; i++) {
        int row = m0 + tm * 8 + i;
#pragma unroll
        for (int j = 0; j < 4; j++) {
            int col = tn * 4 + j;
            if (col < Nd) {
                float v = acc[i][j] + bias[col];
                if (relu) v = fmaxf(v, 0.f);
                C[(long)row * ldc + col] = v;
            }
        }
    }
}

// ---------------- s2 norms ----------------
__global__ void s2_kernel(const float4* __restrict__ s, float* __restrict__ s2)
{
    int i = blockIdx.x * blockDim.x + threadIdx.x;
    float4 v = s[i];
    s2[i] = v.x * v.x + v.y * v.y + v.z * v.z + v.w * v.w;
}

// ---------------- kNN: warp per query, warp-distributed sorted top-64 ------------
// Queue: 64 ranks, 2 per lane (rank = lane, rank = 32+lane), ascending by value.
// Values stored in "e-space": e = d2 - s2i (monotone in d2). Padding = FLT_MAX.
__global__ __launch_bounds__(WPB * 32) void knn_kernel(
    const float4* __restrict__ s, const float* __restrict__ s2,
    float* __restrict__ kd, int* __restrict__ kj)
{
    __shared__ float4 sj[TJ];
    __shared__ float  s2j[TJ];

    const unsigned F = 0xffffffffu;
    const int lane = threadIdx.x & 31;
    const int warp = threadIdx.x >> 5;
    const int q    = blockIdx.x * WPB + warp;

    const float4 si = s[q];
    const float s2i = s2[q];
    const float m2x = -2.f * si.x, m2y = -2.f * si.y;
    const float m2z = -2.f * si.z, m2w = -2.f * si.w;

    float q0v = FLT_MAX, q1v = FLT_MAX;
    int   q0j = 0,       q1j = 0;
    float thrE = FLT_MAX;              // e-value at rank KNN-1 (row1 lane 7)

    for (int t0 = 0; t0 < NQ; t0 += TJ) {
        __syncthreads();
        sj[threadIdx.x]  = s[t0 + threadIdx.x];
        s2j[threadIdx.x] = s2[t0 + threadIdx.x];
        __syncthreads();

        for (int it = 0; it < TJ / 32; it++) {
            const int ci = it * 32 + lane;
            float4 c = sj[ci];
            float e = fmaf(m2x, c.x,
                      fmaf(m2y, c.y,
                      fmaf(m2z, c.z,
                      fmaf(m2w, c.w, s2j[ci]))));
            unsigned m = __ballot_sync(F, e < thrE);
            if (m) {
                do {
                    const int src = __ffs(m) - 1; m &= m - 1;
                    const float v = __shfl_sync(F, e, src);
                    const int   j = t0 + it * 32 + src;
                    // cooperative insert of (v, j) into distributed sorted list
                    unsigned b0 = __ballot_sync(F, q0v < v);
                    unsigned b1 = __ballot_sync(F, q1v < v);
                    const int p = __popc(b0) + __popc(b1);
                    float s0v = __shfl_up_sync(F, q0v, 1);
                    int   s0j = __shfl_up_sync(F, q0j, 1);
                    float s1v = __shfl_up_sync(F, q1v, 1);
                    int   s1j = __shfl_up_sync(F, q1j, 1);
                    const float w31v = __shfl_sync(F, q0v, 31);
                    const int   w31j = __shfl_sync(F, q0j, 31);
                    if (lane == 0) { s1v = w31v; s1j = w31j; }
                    const int r1 = 32 + lane;
                    if (lane == p)      { q0v = v;   q0j = j;   }
                    else if (lane > p)  { q0v = s0v; q0j = s0j; }
                    if (r1 == p)        { q1v = v;   q1j = j;   }
                    else if (r1 > p)    { q1v = s1v; q1j = s1j; }
                } while (m);
                thrE = __shfl_sync(F, q1v, 7);   // rank 39
            }
        }
    }

    // write ranks 0..39 as true d2 = e + s2i
    kd[q * KNN + lane] = q0v + s2i;
    kj[q * KNN + lane] = q0j;
    if (lane < KNN - 32) {
        kd[q * KNN + 32 + lane] = q1v + s2i;
        kj[q * KNN + 32 + lane] = q1j;
    }
}

// ---------------- aggregate: warp per query, mean||max of h[idx]*w ---------------
__global__ void aggregate_kernel(
    const float* __restrict__ h, const float* __restrict__ kd,
    const int* __restrict__ kj, float* __restrict__ xcat)
{
    int gw   = (blockIdx.x * blockDim.x + threadIdx.x) >> 5;  // query
    int lane = threadIdx.x & 31;

    const float* dd = kd + gw * KNN;
    const int*   jj = kj + gw * KNN;

    float m0 = 0.f, m1 = 0.f;
    float x0 = -FLT_MAX, x1 = -FLT_MAX;
#pragma unroll
    for (int k = 0; k < KNN; k++) {
        int   j = jj[k];                                  // broadcast load
        float w = expf(-10.f * fmaxf(dd[k], 0.f));
        float v0 = h[j * PROP + lane] * w;                // coalesced 128B
        float v1 = h[j * PROP + 32 + lane] * w;
        m0 += v0; m1 += v1;
        x0 = fmaxf(x0, v0); x1 = fmaxf(x1, v1);
    }
    float* out = xcat + (long)gw * 256 + 128;
    const float inv = 1.f / (float)KNN;
    out[lane]      = m0 * inv;
    out[32 + lane] = m1 * inv;
    out[64 + lane] = x0;
    out[96 + lane] = x1;
}

// =================================================================================
extern "C" void kernel_launch(void* const* d_in, const int* in_sizes, int n_in,
                              void* d_out, int out_size)
{
    const float* x    = (const float*)d_in[0];
    const float* fc1W = (const float*)d_in[1];
    const float* fc1b = (const float*)d_in[2];
    const float* fc2W = (const float*)d_in[3];
    const float* fc2b = (const float*)d_in[4];
    const float* gsW  = (const float*)d_in[5];
    const float* gsb  = (const float*)d_in[6];
    const float* ghW  = (const float*)d_in[7];
    const float* ghb  = (const float*)d_in[8];
    const float* goW  = (const float*)d_in[9];
    const float* gob  = (const float*)d_in[10];
    const float* d1W  = (const float*)d_in[11];
    const float* d1b  = (const float*)d_in[12];
    const float* d2W  = (const float*)d_in[13];
    const float* d2b  = (const float*)d_in[14];
    const float* d3W  = (const float*)d_in[15];
    const float* d3b  = (const float*)d_in[16];
    const float* fc3W = (const float*)d_in[17];
    const float* fc3b = (const float*)d_in[18];
    const float* fc4W = (const float*)d_in[19];
    const float* fc4b = (const float*)d_in[20];
    float* out = (float*)d_out;

    float *t1, *t2, *xcat, *xg, *s, *s2n, *h, *kd;
    int *kj;
    cudaGetSymbolAddress((void**)&t1,   g_t1);
    cudaGetSymbolAddress((void**)&t2,   g_t2);
    cudaGetSymbolAddress((void**)&xcat, g_xcat);
    cudaGetSymbolAddress((void**)&xg,   g_xg);
    cudaGetSymbolAddress((void**)&s,    g_s);
    cudaGetSymbolAddress((void**)&s2n,  g_s2);
    cudaGetSymbolAddress((void**)&h,    g_h);
    cudaGetSymbolAddress((void**)&kd,   g_kd);
    cudaGetSymbolAddress((void**)&kj,   g_kj);

    const int GB = NQ / 64;  // gemm grid

    // fc1, fc2 (x lives in xcat[:, :128] with row stride 256 from here on)
    gemm_kernel<<<GB, 256>>>(x, 9, fc1W, fc1b, t1, HID, 9, HID, 1);
    gemm_kernel<<<GB, 256>>>(t1, HID, fc2W, fc2b, xcat, 256, HID, HID, 1);

    for (int l = 0; l < 4; l++) {
        gemm_kernel<<<GB, 256>>>(xcat, 256, gsW + l * HID * SPACE, gsb + l * SPACE,
                                 s, SPACE, HID, SPACE, 0);
        gemm_kernel<<<GB, 256>>>(xcat, 256, ghW + l * HID * PROP, ghb + l * PROP,
                                 h, PROP, HID, PROP, 0);
        s2_kernel<<<NQ / 256, 256>>>((const float4*)s, s2n);
        knn_kernel<<<NQ / WPB, WPB * 32>>>((const float4*)s, s2n, kd, kj);
        aggregate_kernel<<<NQ / 8, 256>>>(h, kd, kj, xcat);
        // lin_out: [x | mean | max] (Kd=256) -> xg
        gemm_kernel<<<GB, 256>>>(xcat, 256, goW + l * 256 * HID, gob + l * HID,
                                 xg, HID, 256, HID, 0);
        gemm_kernel<<<GB, 256>>>(xg, HID, d1W + l * HID * HID, d1b + l * HID,
                                 t1, HID, HID, HID, 1);
        gemm_kernel<<<GB, 256>>>(t1, HID, d2W + l * HID * HID, d2b + l * HID,
                                 t2, HID, HID, HID, 1);
        gemm_kernel<<<GB, 256>>>(t2, HID, d3W + l * HID * HID, d3b + l * HID,
                                 xcat, 256, HID, HID, 1);
    }

    gemm_kernel<<<GB, 256>>>(xcat, 256, fc3W, fc3b, t1, HID, HID, HID, 1);
    gemm_kernel<<<GB, 256>>>(t1, HID, fc4W, fc4b, out, 4, HID, 4, 0);
}